// round 11
// baseline (speedup 1.0000x reference)
#include <cuda_runtime.h>

#define TPB   256
#define OPT   64             // output-threads per block (oid); 4 kg groups
#define S_OUT 64             // outputs per block (1 per oid)
#define M     11
#define T     4096
#define BB    32
#define NA    (S_OUT + 20)   // 84 amplitude window entries
#define NU    (S_OUT + 10)   // 74 sample window entries

__global__ void __launch_bounds__(TPB, 5)    // regs <= 51 -> 40 warps/SM resident
gmp_kernel(const float2* __restrict__ x,
           const float*  __restrict__ W,
           float2* __restrict__ out)
{
    __shared__ float  Ak[4][NA + 4];     // amplitude powers per k
    __shared__ float2 U  [NU + 2];       // complex samples window
    __shared__ __align__(16) float wsAll[16 + 44 * 12];  // [0..10]=W0, W1 rows padded to 12
    __shared__ float  pc[3][OPT][12];    // k-partials from kg=1..3 (padded rows)

    const int b   = blockIdx.y;
    const int t0  = blockIdx.x * S_OUT;
    const int tid = threadIdx.x;
    const int oid = tid & (OPT - 1);     // 0..63
    const int kg  = tid >> 6;            // 0..3 : the k owned (warps 0-1 are kg0, etc.)
    const float2* xb = x + (size_t)b * T;

    // ---- stage amplitude powers: Ak[k][i] = |u(t0+i-20)|^(k+1), i in [0,84) ----
    if (tid < NA) {
        int pos = t0 + tid - 20;
        float re = 0.f, im = 0.f;
        if (pos >= 0) { float2 v = xb[pos]; re = v.x; im = v.y; }
        float a2 = re * re + im * im;
        float a  = sqrtf(a2);
        Ak[0][tid] = a; Ak[1][tid] = a2; Ak[2][tid] = a2 * a; Ak[3][tid] = a2 * a2;
    }
    // ---- stage samples: U[i] = u(t0+i-10), i in [0,74) ----
    else if (tid >= 128 && tid < 128 + NU) {
        int i = tid - 128;
        int pos = t0 + i - 10;
        float re = 0.f, im = 0.f;
        if (pos >= 0) { float2 v = xb[pos]; re = v.x; im = v.y; }
        U[i] = make_float2(re, im);
    }
    // ---- stage weights: one W1 row per thread (straight-line, no div/mod) ----
    if (tid >= 208 && tid < 224) {
        int j = tid - 208;
        wsAll[j] = (j < M) ? W[j] : 0.f;
    } else if (tid >= 160 && tid < 204) {
        int r = tid - 160;                    // row 0..43 (r = k*11 + l)
        const float* src = W + 11 + r * 11;
        float* dst = wsAll + 16 + r * 12;
#pragma unroll
        for (int m = 0; m < M; m++) dst[m] = src[m];
        dst[11] = 0.f;
    }
    __syncthreads();

    // Output t = t0 + oid; this thread covers k = kg only.
    float c[M];
    if (kg == 0) {
#pragma unroll
        for (int m = 0; m < M; m++) c[m] = wsAll[m];
    } else {
#pragma unroll
        for (int m = 0; m < M; m++) c[m] = 0.f;
    }

    {
        float win[21];                        // A_kg(t-20+s), s=0..20 (scalar: 4B aligned)
#pragma unroll
        for (int s = 0; s < 21; s++) win[s] = Ak[kg][oid + s];

        const float* wrow = wsAll + 16 + (kg * M) * 12;
#pragma unroll
        for (int l = 0; l < M; l++) {
            float4 wa = *(const float4*)(wrow + l * 12 + 0);   // broadcast LDS.128
            float4 wb = *(const float4*)(wrow + l * 12 + 4);
            float4 wc = *(const float4*)(wrow + l * 12 + 8);
            c[0]  = fmaf(win[l + 0],  wa.x, c[0]);
            c[1]  = fmaf(win[l + 1],  wa.y, c[1]);
            c[2]  = fmaf(win[l + 2],  wa.z, c[2]);
            c[3]  = fmaf(win[l + 3],  wa.w, c[3]);
            c[4]  = fmaf(win[l + 4],  wb.x, c[4]);
            c[5]  = fmaf(win[l + 5],  wb.y, c[5]);
            c[6]  = fmaf(win[l + 6],  wb.z, c[6]);
            c[7]  = fmaf(win[l + 7],  wb.w, c[7]);
            c[8]  = fmaf(win[l + 8],  wc.x, c[8]);
            c[9]  = fmaf(win[l + 9],  wc.y, c[9]);
            c[10] = fmaf(win[l + 10], wc.z, c[10]);
        }
    }

    // ---- exchange k-partials (kg 1..3 publish; conflict-free: addr = oid*12+m) ----
    if (kg != 0) {
#pragma unroll
        for (int m = 0; m < M; m++) pc[kg - 1][oid][m] = c[m];
    }
    __syncthreads();

    if (kg == 0) {   // warps 0-1: combine + epilogue, no intra-warp divergence
        float ar = 0.f, ai = 0.f;
#pragma unroll
        for (int m = 0; m < M; m++) {
            float cm = c[m] + pc[0][oid][m] + pc[1][oid][m] + pc[2][oid][m];
            float2 u = U[oid + m];            // float2 array -> 8B aligned
            ar = fmaf(u.x, cm, ar);
            ai = fmaf(u.y, cm, ai);
        }
        out[(size_t)b * T + t0 + oid] = make_float2(ar, ai);
    }
}

extern "C" void kernel_launch(void* const* d_in, const int* in_sizes, int n_in,
                              void* d_out, int out_size)
{
    const float2* x = (const float2*)d_in[0];   // (32, 4096, 2) f32
    // d_in[1] = h_0 (unused by reference)
    const float*  W = (const float*)d_in[2];    // (1, 495) f32
    float2* out = (float2*)d_out;               // (32, 4096, 2) f32

    dim3 grid(T / S_OUT, BB);                   // (64, 32) = 2048 blocks
    gmp_kernel<<<grid, TPB>>>(x, W, out);
}